// round 3
// baseline (speedup 1.0000x reference)
#include <cuda_runtime.h>
#include <math.h>

// Problem constants
#define NB 8
#define NL 2048
#define ND 512
#define BLD (NB*NL*ND)      // 8,388,608 elems per tensor
#define BLL_ ((long long)NB*NL*NL)  // 33,554,432 per direction score matrix

// Scratch (device globals: allocation-free per harness rules)
__device__ float g_q[2ULL*BLD];   // Q per direction; reused as context output after PV
__device__ float g_k[2ULL*BLD];
__device__ float g_v[2ULL*BLD];
__device__ float g_g[2ULL*BLD];   // gate pre-activations
__device__ float g_s[2ULL*BLL_];  // scores / probs

// ---------------------------------------------------------------------------
// Generic tiled FP32 GEMM.
//   BT = true : C[m,n] = alpha * sum_k A[m,k] * B[n,k]  (+bias[n])   "NT"
//   BT = false: C[m,n] = alpha * sum_k A[m,k] * B[k,n]  (+bias[n])   "NN"
// Tiles: 128x128x8, 256 threads, 8x8 per-thread microtile.
// Requires M%128==0, N%128==0, K%8==0 (all shapes here satisfy this).
// Batched via blockIdx.z with element strides sA/sB/sC.
// ---------------------------------------------------------------------------
template<bool BT>
__global__ __launch_bounds__(256, 2)
void gemm_k(const float* __restrict__ A, const float* __restrict__ Bm,
            const float* __restrict__ bias, float* __restrict__ C,
            int M, int N, int K, float alpha,
            long long sA, long long sB, long long sC)
{
    constexpr int BM = 128, BN = 128, BK = 8;
    __shared__ float As[BK][BM];
    __shared__ float Bs[BK][BN];

    A  += (long long)blockIdx.z * sA;
    Bm += (long long)blockIdx.z * sB;
    C  += (long long)blockIdx.z * sC;

    const int tid = threadIdx.x;
    const int tx = tid & 15;        // 0..15 -> N microtiles
    const int ty = tid >> 4;        // 0..15 -> M microtiles
    const int rowBase = blockIdx.y * BM;
    const int colBase = blockIdx.x * BN;

    // A global-load mapping: 128 rows x 8 k, float4 per thread (2 threads/row)
    const int aRow = tid >> 1;
    const int aK   = (tid & 1) * 4;
    const float* Ap = A + (long long)(rowBase + aRow) * K + aK;

    // B global-load mapping
    int bR, bK_;
    const float* Bp;
    if (BT) {  // B is (N,K) row-major: same pattern as A over N rows
        bR  = tid >> 1;
        bK_ = (tid & 1) * 4;
        Bp  = Bm + (long long)(colBase + bR) * K + bK_;
    } else {   // B is (K,N) row-major: 8 k-rows x 32 threads x float4
        bK_ = tid >> 5;           // 0..7
        bR  = (tid & 31) * 4;     // 0..124
        Bp  = Bm + (long long)bK_ * N + colBase + bR;
    }

    float acc[8][8];
    #pragma unroll
    for (int i = 0; i < 8; i++)
        #pragma unroll
        for (int j = 0; j < 8; j++) acc[i][j] = 0.f;

    for (int kt = 0; kt < K; kt += BK) {
        float4 a4 = *reinterpret_cast<const float4*>(Ap);
        Ap += BK;
        float4 b4 = *reinterpret_cast<const float4*>(Bp);
        if (BT) Bp += BK; else Bp += (long long)BK * N;

        As[aK + 0][aRow] = a4.x;
        As[aK + 1][aRow] = a4.y;
        As[aK + 2][aRow] = a4.z;
        As[aK + 3][aRow] = a4.w;
        if (BT) {
            Bs[bK_ + 0][bR] = b4.x;
            Bs[bK_ + 1][bR] = b4.y;
            Bs[bK_ + 2][bR] = b4.z;
            Bs[bK_ + 3][bR] = b4.w;
        } else {
            *reinterpret_cast<float4*>(&Bs[bK_][bR]) = b4;
        }
        __syncthreads();

        #pragma unroll
        for (int kk = 0; kk < BK; kk++) {
            float ar[8], br[8];
            *reinterpret_cast<float4*>(ar)     = *reinterpret_cast<const float4*>(&As[kk][ty * 8]);
            *reinterpret_cast<float4*>(ar + 4) = *reinterpret_cast<const float4*>(&As[kk][ty * 8 + 4]);
            *reinterpret_cast<float4*>(br)     = *reinterpret_cast<const float4*>(&Bs[kk][tx * 8]);
            *reinterpret_cast<float4*>(br + 4) = *reinterpret_cast<const float4*>(&Bs[kk][tx * 8 + 4]);
            #pragma unroll
            for (int i = 0; i < 8; i++)
                #pragma unroll
                for (int j = 0; j < 8; j++)
                    acc[i][j] = fmaf(ar[i], br[j], acc[i][j]);
        }
        __syncthreads();
    }

    float bv[8];
    #pragma unroll
    for (int j = 0; j < 8; j++)
        bv[j] = bias ? bias[colBase + tx * 8 + j] : 0.f;

    #pragma unroll
    for (int i = 0; i < 8; i++) {
        float4 o0, o1;
        o0.x = alpha * acc[i][0] + bv[0];
        o0.y = alpha * acc[i][1] + bv[1];
        o0.z = alpha * acc[i][2] + bv[2];
        o0.w = alpha * acc[i][3] + bv[3];
        o1.x = alpha * acc[i][4] + bv[4];
        o1.y = alpha * acc[i][5] + bv[5];
        o1.z = alpha * acc[i][6] + bv[6];
        o1.w = alpha * acc[i][7] + bv[7];
        long long off = (long long)(rowBase + ty * 8 + i) * N + colBase + tx * 8;
        *reinterpret_cast<float4*>(&C[off])     = o0;
        *reinterpret_cast<float4*>(&C[off + 4]) = o1;
    }
}

// ---------------------------------------------------------------------------
// Row softmax, in place. One 256-thread CTA per row of length ncols.
// ---------------------------------------------------------------------------
__global__ void softmax_k(float* __restrict__ S, int ncols)
{
    float* row = S + (long long)blockIdx.x * ncols;
    const int tid = threadIdx.x;
    __shared__ float red[8];

    float m = -3.4e38f;
    for (int c = tid; c < ncols; c += 256) m = fmaxf(m, row[c]);
    #pragma unroll
    for (int o = 16; o; o >>= 1) m = fmaxf(m, __shfl_xor_sync(0xffffffffu, m, o));
    if ((tid & 31) == 0) red[tid >> 5] = m;
    __syncthreads();
    m = red[0];
    #pragma unroll
    for (int w = 1; w < 8; w++) m = fmaxf(m, red[w]);

    float sum = 0.f;
    for (int c = tid; c < ncols; c += 256) {
        float e = __expf(row[c] - m);
        row[c] = e;
        sum += e;
    }
    #pragma unroll
    for (int o = 16; o; o >>= 1) sum += __shfl_xor_sync(0xffffffffu, sum, o);
    __syncthreads();            // red reuse
    if ((tid & 31) == 0) red[tid >> 5] = sum;
    __syncthreads();
    sum = 0.f;
    #pragma unroll
    for (int w = 0; w < 8; w++) sum += red[w];

    const float inv = 1.f / sum;
    for (int c = tid; c < ncols; c += 256) row[c] *= inv;
}

// ---------------------------------------------------------------------------
// out = h + sigmoid(gpre) * ctx   (vectorized float4, exact coverage)
// ---------------------------------------------------------------------------
__global__ void finalize_k(const float4* __restrict__ h, const float4* __restrict__ gpre,
                           const float4* __restrict__ ctx, float4* __restrict__ out)
{
    const int i = blockIdx.x * blockDim.x + threadIdx.x;
    float4 hv = h[i], gv = gpre[i], cv = ctx[i];
    float4 o;
    o.x = hv.x + cv.x / (1.f + __expf(-gv.x));
    o.y = hv.y + cv.y / (1.f + __expf(-gv.y));
    o.z = hv.z + cv.z / (1.f + __expf(-gv.z));
    o.w = hv.w + cv.w / (1.f + __expf(-gv.w));
    out[i] = o;
}

// ---------------------------------------------------------------------------
// kernel_launch
// Input order: h_s, h_c, then (W,b) for qs, kc, vc, qc, ks, vs, gs, gc.
// Output: concat(h_s_updated, h_c_updated), 2*B*L*D floats.
// ---------------------------------------------------------------------------
extern "C" void kernel_launch(void* const* d_in, const int* in_sizes, int n_in,
                              void* d_out, int out_size)
{
    const float* h_s = (const float*)d_in[0];
    const float* h_c = (const float*)d_in[1];
    const float *Wqs = (const float*)d_in[2],  *bqs = (const float*)d_in[3];
    const float *Wkc = (const float*)d_in[4],  *bkc = (const float*)d_in[5];
    const float *Wvc = (const float*)d_in[6],  *bvc = (const float*)d_in[7];
    const float *Wqc = (const float*)d_in[8],  *bqc = (const float*)d_in[9];
    const float *Wks = (const float*)d_in[10], *bks = (const float*)d_in[11];
    const float *Wvs = (const float*)d_in[12], *bvs = (const float*)d_in[13];
    const float *Wgs = (const float*)d_in[14], *bgs = (const float*)d_in[15];
    const float *Wgc = (const float*)d_in[16], *bgc = (const float*)d_in[17];
    float* out = (float*)d_out;

    float *q, *k, *v, *g, *s;
    cudaGetSymbolAddress((void**)&q, g_q);
    cudaGetSymbolAddress((void**)&k, g_k);
    cudaGetSymbolAddress((void**)&v, g_v);
    cudaGetSymbolAddress((void**)&g, g_g);
    cudaGetSymbolAddress((void**)&s, g_s);

    const dim3 blk(256);
    const int M = NB * NL;                 // 16384

    // Phase 1: projections (NT GEMM, bias).  dir0 updates h_s; dir1 updates h_c.
    {
        dim3 gp(ND / 128, M / 128, 1);
        gemm_k<true><<<gp, blk>>>(h_s, Wqs, bqs, q,        M, ND, ND, 1.f, 0, 0, 0);
        gemm_k<true><<<gp, blk>>>(h_c, Wkc, bkc, k,        M, ND, ND, 1.f, 0, 0, 0);
        gemm_k<true><<<gp, blk>>>(h_c, Wvc, bvc, v,        M, ND, ND, 1.f, 0, 0, 0);
        gemm_k<true><<<gp, blk>>>(h_s, Wgs, bgs, g,        M, ND, ND, 1.f, 0, 0, 0);
        gemm_k<true><<<gp, blk>>>(h_c, Wqc, bqc, q + BLD,  M, ND, ND, 1.f, 0, 0, 0);
        gemm_k<true><<<gp, blk>>>(h_s, Wks, bks, k + BLD,  M, ND, ND, 1.f, 0, 0, 0);
        gemm_k<true><<<gp, blk>>>(h_s, Wvs, bvs, v + BLD,  M, ND, ND, 1.f, 0, 0, 0);
        gemm_k<true><<<gp, blk>>>(h_c, Wgc, bgc, g + BLD,  M, ND, ND, 1.f, 0, 0, 0);
    }

    // Phase 2a: scores = (1/sqrt(D)) * Q @ K^T, batched over 16 (2 dirs x 8 batches)
    {
        const float alpha = 1.0f / sqrtf((float)ND);
        dim3 gsd(NL / 128, NL / 128, 16);
        gemm_k<true><<<gsd, blk>>>(q, k, nullptr, s, NL, NL, ND, alpha,
                                   (long long)NL * ND, (long long)NL * ND,
                                   (long long)NL * NL);
    }

    // Phase 2b: row softmax (32768 rows of 2048)
    softmax_k<<<16 * NL, 256>>>(s, NL);

    // Phase 2c: context = P @ V (NN GEMM), write over Q buffer (dead after 2a)
    {
        dim3 gc(ND / 128, NL / 128, 16);
        gemm_k<false><<<gc, blk>>>(s, v, nullptr, q, NL, ND, NL, 1.f,
                                   (long long)NL * NL, (long long)NL * ND,
                                   (long long)NL * ND);
    }

    // Phase 3: out = h + sigmoid(g) * ctx
    {
        const int n4 = BLD / 4;               // 2,097,152
        finalize_k<<<n4 / 256, 256>>>((const float4*)h_s, (const float4*)g,
                                      (const float4*)q, (float4*)out);
        finalize_k<<<n4 / 256, 256>>>((const float4*)h_c, (const float4*)(g + BLD),
                                      (const float4*)(q + BLD), (float4*)(out + BLD));
    }
}

// round 4
// speedup vs baseline: 5.4740x; 5.4740x over previous
#include <cuda_runtime.h>
#include <cuda_bf16.h>
#include <math.h>

// Problem constants
#define NB 8
#define NL 2048
#define ND 512
#define BLD (NB*NL*ND)              // 8,388,608 elems per tensor
#define BLL_ ((long long)NB*NL*NL)  // 33,554,432 per direction score matrix

// Scratch (device globals: allocation-free per harness rules)
__device__ unsigned short g_hbf[2ULL*BLD];        // h_s, h_c in bf16
__device__ unsigned short g_wbf[8ULL*512*512];    // 8 weights bf16
__device__ unsigned short g_qb[2ULL*BLD];
__device__ unsigned short g_kb[2ULL*BLD];
__device__ unsigned short g_vb[2ULL*BLD];
__device__ unsigned short g_gb[2ULL*BLD];
__device__ float          g_s [2ULL*BLL_];        // fp32 scores
__device__ unsigned short g_pb[2ULL*BLL_];        // bf16 probs
__device__ float          g_ctx[2ULL*BLD];        // fp32 context

// ---------------------------------------------------------------------------
// PTX helpers
// ---------------------------------------------------------------------------
__device__ __forceinline__ unsigned smem_u32(const void* p) {
    return (unsigned)__cvta_generic_to_shared(p);
}
__device__ __forceinline__ void cp16(unsigned dst, const void* src) {
    asm volatile("cp.async.cg.shared.global [%0], [%1], 16;\n" :: "r"(dst), "l"(src));
}
__device__ __forceinline__ void cp_commit() { asm volatile("cp.async.commit_group;\n"); }
template<int N> __device__ __forceinline__ void cp_wait() {
    asm volatile("cp.async.wait_group %0;\n" :: "n"(N));
}
__device__ __forceinline__ void ldsm4(unsigned* r, unsigned a) {
    asm volatile("ldmatrix.sync.aligned.m8n8.x4.shared.b16 {%0,%1,%2,%3}, [%4];\n"
        : "=r"(r[0]), "=r"(r[1]), "=r"(r[2]), "=r"(r[3]) : "r"(a));
}
__device__ __forceinline__ void ldsm2(unsigned* r, unsigned a) {
    asm volatile("ldmatrix.sync.aligned.m8n8.x2.shared.b16 {%0,%1}, [%2];\n"
        : "=r"(r[0]), "=r"(r[1]) : "r"(a));
}
__device__ __forceinline__ void ldsm2t(unsigned* r, unsigned a) {
    asm volatile("ldmatrix.sync.aligned.m8n8.x2.trans.shared.b16 {%0,%1}, [%2];\n"
        : "=r"(r[0]), "=r"(r[1]) : "r"(a));
}
__device__ __forceinline__ void mma16816(float* c, const unsigned* a, const unsigned* b) {
    asm volatile("mma.sync.aligned.m16n8k16.row.col.f32.bf16.bf16.f32 "
        "{%0,%1,%2,%3}, {%4,%5,%6,%7}, {%8,%9}, {%0,%1,%2,%3};\n"
        : "+f"(c[0]), "+f"(c[1]), "+f"(c[2]), "+f"(c[3])
        : "r"(a[0]), "r"(a[1]), "r"(a[2]), "r"(a[3]), "r"(b[0]), "r"(b[1]));
}
__device__ __forceinline__ unsigned short f2bfu(float x) {
    return __bfloat16_as_ushort(__float2bfloat16_rn(x));
}
__device__ __forceinline__ float bfu2f(unsigned short u) {
    return __bfloat162float(__ushort_as_bfloat16(u));
}

// ---------------------------------------------------------------------------
// bf16 tensor-core GEMM, fp32 accumulate.
//   BT = true : C[m,n] = alpha*sum_k A[m,k]*B[n,k] (+bias[n])  "NT", B is NxK
//   BT = false: C[m,n] = alpha*sum_k A[m,k]*B[k,n]             "NN", B is KxN
//   OUT_BF: write bf16, else fp32
// CTA tile 128x128x32, 256 threads = 8 warps (2x4), warp tile 64x32.
// Requires M%128==0, N%128==0, K%32==0 (all shapes satisfy).
// ---------------------------------------------------------------------------
template<bool BT, bool OUT_BF>
__global__ __launch_bounds__(256, 2)
void gemm_bf16(const unsigned short* __restrict__ A,
               const unsigned short* __restrict__ Bm,
               const float* __restrict__ bias, void* __restrict__ Cv,
               int M, int N, int K, float alpha,
               long long sA, long long sB, long long sC)
{
    constexpr int LDA = 40;                 // 32 + 8 pad (bf16 elems)
    constexpr int ASZ = 128 * LDA;          // per-buffer A region (5120)
    constexpr int LDB = BT ? 40 : 136;      // NT: [128][40], NN: [32][136]
    constexpr int BSZ = BT ? 128 * 40 : 32 * 136;
    constexpr int BOFF = 2 * ASZ;           // 10240
    __shared__ __align__(16) unsigned short sm[BOFF + 2 * BSZ];

    A  += (long long)blockIdx.z * sA;
    Bm += (long long)blockIdx.z * sB;

    const int tid  = threadIdx.x;
    const int lane = tid & 31;
    const int wid  = tid >> 5;
    const int warpM = wid >> 2;             // 0..1 (64 rows each)
    const int warpN = wid & 3;              // 0..3 (32 cols each)
    const int rowBase = blockIdx.y * 128;
    const int colBase = blockIdx.x * 128;

    float acc[4][4][4];
    #pragma unroll
    for (int i = 0; i < 4; i++)
        #pragma unroll
        for (int j = 0; j < 4; j++)
            #pragma unroll
            for (int e = 0; e < 4; e++) acc[i][j][e] = 0.f;

    auto load_tile = [&](int kt, int buf) {
        const int k0 = kt * 32;
        // A tile: 128 rows x 32 bf16; 16B per cp; 2 chunks per thread
        {
            const int r0 = tid >> 2, seg = tid & 3;
            #pragma unroll
            for (int c = 0; c < 2; c++) {
                int row = r0 + c * 64;
                const unsigned short* src = A + (long long)(rowBase + row) * K + k0 + seg * 8;
                cp16(smem_u32(&sm[buf * ASZ + row * LDA + seg * 8]), src);
            }
        }
        if (BT) { // B is NxK row-major -> smem [n][k]
            const int r0 = tid >> 2, seg = tid & 3;
            #pragma unroll
            for (int c = 0; c < 2; c++) {
                int row = r0 + c * 64;
                const unsigned short* src = Bm + (long long)(colBase + row) * K + k0 + seg * 8;
                cp16(smem_u32(&sm[BOFF + buf * BSZ + row * LDB + seg * 8]), src);
            }
        } else {  // B is KxN row-major -> smem [k][n]
            const int kr = tid >> 3, seg0 = tid & 7;
            #pragma unroll
            for (int c = 0; c < 2; c++) {
                int seg = seg0 + c * 8;
                const unsigned short* src = Bm + (long long)(k0 + kr) * N + colBase + seg * 8;
                cp16(smem_u32(&sm[BOFF + buf * BSZ + kr * LDB + seg * 8]), src);
            }
        }
    };

    auto compute_tile = [&](int buf) {
        #pragma unroll
        for (int ks = 0; ks < 32; ks += 16) {
            unsigned a[4][4], b[4][2];
            #pragma unroll
            for (int mi = 0; mi < 4; mi++) {
                int row = warpM * 64 + mi * 16 + (lane & 7) + (lane & 8);
                int col = ks + ((lane & 16) >> 1);
                ldsm4(a[mi], smem_u32(&sm[buf * ASZ + row * LDA + col]));
            }
            #pragma unroll
            for (int ni = 0; ni < 4; ni++) {
                if (BT) {
                    int row = warpN * 32 + ni * 8 + (lane & 7);
                    int col = ks + (lane & 8);
                    ldsm2(b[ni], smem_u32(&sm[BOFF + buf * BSZ + row * LDB + col]));
                } else {
                    int row = ks + (lane & 7) + (lane & 8);
                    int col = warpN * 32 + ni * 8;
                    ldsm2t(b[ni], smem_u32(&sm[BOFF + buf * BSZ + row * LDB + col]));
                }
            }
            #pragma unroll
            for (int mi = 0; mi < 4; mi++)
                #pragma unroll
                for (int ni = 0; ni < 4; ni++)
                    mma16816(acc[mi][ni], a[mi], b[ni]);
        }
    };

    const int ntiles = K / 32;
    load_tile(0, 0);
    cp_commit();
    int buf = 0;
    for (int kt = 0; kt < ntiles; kt++) {
        const bool has_next = (kt + 1 < ntiles);
        if (has_next) { load_tile(kt + 1, buf ^ 1); cp_commit(); }
        if (has_next) cp_wait<1>(); else cp_wait<0>();
        __syncthreads();
        compute_tile(buf);
        __syncthreads();
        buf ^= 1;
    }

    // Epilogue
    const int rr = lane >> 2, cc = (lane & 3) << 1;
    #pragma unroll
    for (int mi = 0; mi < 4; mi++) {
        const int row0 = rowBase + warpM * 64 + mi * 16 + rr;
        #pragma unroll
        for (int ni = 0; ni < 4; ni++) {
            const int col = colBase + warpN * 32 + ni * 8 + cc;
            float b0 = 0.f, b1 = 0.f;
            if (bias) { b0 = bias[col]; b1 = bias[col + 1]; }
            float x0 = alpha * acc[mi][ni][0] + b0;
            float x1 = alpha * acc[mi][ni][1] + b1;
            float x2 = alpha * acc[mi][ni][2] + b0;
            float x3 = alpha * acc[mi][ni][3] + b1;
            if (OUT_BF) {
                unsigned short* Cb = (unsigned short*)Cv + (long long)blockIdx.z * sC;
                unsigned p0 = (unsigned)f2bfu(x0) | ((unsigned)f2bfu(x1) << 16);
                unsigned p1 = (unsigned)f2bfu(x2) | ((unsigned)f2bfu(x3) << 16);
                *(unsigned*)&Cb[(long long)row0 * N + col] = p0;
                *(unsigned*)&Cb[(long long)(row0 + 8) * N + col] = p1;
            } else {
                float* Cf = (float*)Cv + (long long)blockIdx.z * sC;
                *(float2*)&Cf[(long long)row0 * N + col] = make_float2(x0, x1);
                *(float2*)&Cf[(long long)(row0 + 8) * N + col] = make_float2(x2, x3);
            }
        }
    }
}

// ---------------------------------------------------------------------------
// fp32 -> bf16 conversion (float4 -> 4x bf16 per thread)
// ---------------------------------------------------------------------------
__global__ void f2bf_k(const float4* __restrict__ in, uint2* __restrict__ out)
{
    const int i = blockIdx.x * 256 + threadIdx.x;
    float4 v = in[i];
    uint2 o;
    o.x = (unsigned)f2bfu(v.x) | ((unsigned)f2bfu(v.y) << 16);
    o.y = (unsigned)f2bfu(v.z) | ((unsigned)f2bfu(v.w) << 16);
    out[i] = o;
}

// ---------------------------------------------------------------------------
// Row softmax: fp32 scores in, bf16 probs out. Online max/sum, 2 passes.
// One 256-thread CTA per row (ncols4 float4 per row = 512).
// ---------------------------------------------------------------------------
__global__ void softmax_k(const float4* __restrict__ S4, uint2* __restrict__ P2, int ncols4)
{
    const long long rowoff = (long long)blockIdx.x * ncols4;
    const float4* row = S4 + rowoff;
    const int tid = threadIdx.x;

    float m = -3.4e38f, s = 0.f;
    for (int c = tid; c < ncols4; c += 256) {
        float4 v = row[c];
        float lm = fmaxf(fmaxf(v.x, v.y), fmaxf(v.z, v.w));
        float nm = fmaxf(m, lm);
        s = s * __expf(m - nm)
          + __expf(v.x - nm) + __expf(v.y - nm) + __expf(v.z - nm) + __expf(v.w - nm);
        m = nm;
    }
    #pragma unroll
    for (int o = 16; o; o >>= 1) {
        float om = __shfl_xor_sync(0xffffffffu, m, o);
        float os = __shfl_xor_sync(0xffffffffu, s, o);
        float nm = fmaxf(m, om);
        s = s * __expf(m - nm) + os * __expf(om - nm);
        m = nm;
    }
    __shared__ float smx[8], ssx[8];
    if ((tid & 31) == 0) { smx[tid >> 5] = m; ssx[tid >> 5] = s; }
    __syncthreads();
    float M = smx[0], S = ssx[0];
    #pragma unroll
    for (int w = 1; w < 8; w++) {
        float om = smx[w], os = ssx[w];
        float nm = fmaxf(M, om);
        S = S * __expf(M - nm) + os * __expf(om - nm);
        M = nm;
    }
    const float inv = 1.f / S;

    uint2* prow = P2 + rowoff;
    for (int c = tid; c < ncols4; c += 256) {
        float4 v = row[c];
        float e0 = __expf(v.x - M) * inv;
        float e1 = __expf(v.y - M) * inv;
        float e2 = __expf(v.z - M) * inv;
        float e3 = __expf(v.w - M) * inv;
        uint2 o;
        o.x = (unsigned)f2bfu(e0) | ((unsigned)f2bfu(e1) << 16);
        o.y = (unsigned)f2bfu(e2) | ((unsigned)f2bfu(e3) << 16);
        prow[c] = o;
    }
}

// ---------------------------------------------------------------------------
// out = h + sigmoid(gpre_bf16) * ctx
// ---------------------------------------------------------------------------
__global__ void finalize_k(const float4* __restrict__ h, const uint2* __restrict__ gpre,
                           const float4* __restrict__ ctx, float4* __restrict__ out)
{
    const int i = blockIdx.x * 256 + threadIdx.x;
    float4 hv = h[i], cv = ctx[i];
    uint2 gv = gpre[i];
    float g0 = bfu2f((unsigned short)(gv.x & 0xffff));
    float g1 = bfu2f((unsigned short)(gv.x >> 16));
    float g2 = bfu2f((unsigned short)(gv.y & 0xffff));
    float g3 = bfu2f((unsigned short)(gv.y >> 16));
    float4 o;
    o.x = hv.x + cv.x / (1.f + __expf(-g0));
    o.y = hv.y + cv.y / (1.f + __expf(-g1));
    o.z = hv.z + cv.z / (1.f + __expf(-g2));
    o.w = hv.w + cv.w / (1.f + __expf(-g3));
    out[i] = o;
}

// ---------------------------------------------------------------------------
// kernel_launch
// Inputs: h_s, h_c, then (W,b) for qs, kc, vc, qc, ks, vs, gs, gc.
// Output: concat(h_s_updated, h_c_updated), 2*B*L*D floats.
// ---------------------------------------------------------------------------
extern "C" void kernel_launch(void* const* d_in, const int* in_sizes, int n_in,
                              void* d_out, int out_size)
{
    (void)in_sizes; (void)n_in; (void)out_size;
    const float* h_s = (const float*)d_in[0];
    const float* h_c = (const float*)d_in[1];
    const float* W[8]; const float* bia[8];
    for (int i = 0; i < 8; i++) { W[i] = (const float*)d_in[2 + 2*i]; bia[i] = (const float*)d_in[3 + 2*i]; }
    // order: 0=qs 1=kc 2=vc 3=qc 4=ks 5=vs 6=gs 7=gc
    float* out = (float*)d_out;

    unsigned short *hbf, *wbf, *qb, *kb, *vb, *gb, *pb;
    float *s, *ctx;
    cudaGetSymbolAddress((void**)&hbf, g_hbf);
    cudaGetSymbolAddress((void**)&wbf, g_wbf);
    cudaGetSymbolAddress((void**)&qb,  g_qb);
    cudaGetSymbolAddress((void**)&kb,  g_kb);
    cudaGetSymbolAddress((void**)&vb,  g_vb);
    cudaGetSymbolAddress((void**)&gb,  g_gb);
    cudaGetSymbolAddress((void**)&pb,  g_pb);
    cudaGetSymbolAddress((void**)&s,   g_s);
    cudaGetSymbolAddress((void**)&ctx, g_ctx);

    const int M = NB * NL;      // 16384
    const long long WSZ = 512 * 512;

    // Convert inputs to bf16
    f2bf_k<<<BLD/4/256, 256>>>((const float4*)h_s, (uint2*)hbf);
    f2bf_k<<<BLD/4/256, 256>>>((const float4*)h_c, (uint2*)(hbf + BLD));
    for (int i = 0; i < 8; i++)
        f2bf_k<<<WSZ/4/256, 256>>>((const float4*)W[i], (uint2*)(wbf + i*WSZ));

    const unsigned short* hsb = hbf;
    const unsigned short* hcb = hbf + BLD;

    // Phase 1: projections (NT, bias, bf16 out)
    {
        dim3 gp(ND/128, M/128, 1), blk(256);
        gemm_bf16<true,true><<<gp,blk>>>(hsb, wbf+0*WSZ, bia[0], qb,       M, ND, ND, 1.f, 0,0,0); // qs
        gemm_bf16<true,true><<<gp,blk>>>(hcb, wbf+1*WSZ, bia[1], kb,       M, ND, ND, 1.f, 0,0,0); // kc
        gemm_bf16<true,true><<<gp,blk>>>(hcb, wbf+2*WSZ, bia[2], vb,       M, ND, ND, 1.f, 0,0,0); // vc
        gemm_bf16<true,true><<<gp,blk>>>(hsb, wbf+6*WSZ, bia[6], gb,       M, ND, ND, 1.f, 0,0,0); // gs
        gemm_bf16<true,true><<<gp,blk>>>(hcb, wbf+3*WSZ, bia[3], qb+BLD,   M, ND, ND, 1.f, 0,0,0); // qc
        gemm_bf16<true,true><<<gp,blk>>>(hsb, wbf+4*WSZ, bia[4], kb+BLD,   M, ND, ND, 1.f, 0,0,0); // ks
        gemm_bf16<true,true><<<gp,blk>>>(hsb, wbf+5*WSZ, bia[5], vb+BLD,   M, ND, ND, 1.f, 0,0,0); // vs
        gemm_bf16<true,true><<<gp,blk>>>(hcb, wbf+7*WSZ, bia[7], gb+BLD,   M, ND, ND, 1.f, 0,0,0); // gc
    }

    // Phase 2a: scores = alpha * Q @ K^T (NT, fp32 out), 16 batches
    {
        const float alpha = 1.0f / sqrtf((float)ND);
        dim3 gq(NL/128, NL/128, 16), blk(256);
        gemm_bf16<true,false><<<gq,blk>>>(qb, kb, nullptr, s, NL, NL, ND, alpha,
                                          (long long)NL*ND, (long long)NL*ND,
                                          (long long)NL*NL);
    }

    // Phase 2b: softmax -> bf16 probs
    softmax_k<<<16*NL, 256>>>((const float4*)s, (uint2*)pb, NL/4);

    // Phase 2c: context = P @ V (NN, fp32 out)
    {
        dim3 gc(ND/128, NL/128, 16), blk(256);
        gemm_bf16<false,false><<<gc,blk>>>(pb, vb, nullptr, ctx, NL, ND, NL, 1.f,
                                           (long long)NL*NL, (long long)NL*ND,
                                           (long long)NL*ND);
    }

    // Phase 3: out = h + sigmoid(g) * ctx
    {
        const int nblk = BLD/4/256;
        finalize_k<<<nblk, 256>>>((const float4*)h_s, (const uint2*)gb,
                                  (const float4*)ctx, (float4*)out);
        finalize_k<<<nblk, 256>>>((const float4*)h_c, (const uint2*)(gb + BLD),
                                  (const float4*)(ctx + BLD), (float4*)(out + BLD));
    }
}